// round 12
// baseline (speedup 1.0000x reference)
#include <cuda_runtime.h>
#include <cuda_bf16.h>

#define BATCH 16
#define MP 30      // max people
#define NJ 17      // joints
#define AD 17      // ae tag dim
#define RES 512
#define RR (RES*RES)

#define JPI (MP * NJ)                    // 510 joints per image
#define NPT (BATCH * MP)                 // 480 person-tasks
#define GRID_CTAS (BATCH + NPT)          // 16 reduce + 480 gather = 496
#define BT 512

// per-person complete stats (written unconditionally by gather CTAs)
__device__ float g_psum[NPT * AD];       // masked tag sums per (person, d)
__device__ float g_psq [NPT];            // per-person sum of sqv
__device__ float g_pcnt[NPT];            // per-person valid count
// per-image producer counters (zero-init; consumer resets each replay)
__device__ unsigned g_done[BATCH];

__global__ __launch_bounds__(BT, 1)
void ae_onekernel(const float* __restrict__ tags,
                  const int*   __restrict__ joints,
                  float*       __restrict__ out)
{
    const int tid = threadIdx.x;
    const unsigned FULL = 0xffffffffu;

    // =============== GATHER role: one person per CTA (blocks 16..495) ======
    if (blockIdx.x >= BATCH) {
        const int pt = blockIdx.x - BATCH;   // person-task id
        const int b  = pt / MP;
        const int m  = pt % MP;

        __shared__ float sh[NJ][AD + 1];     // masked tag matrix for this person

        if (tid < NJ * AD) {
            const int j = tid / AD;
            const int d = tid % AD;
            const int jj = b * JPI + m * NJ + j;

            const int idx = __ldg(&joints[jj * 2 + 0]);
            const int vis = __ldg(&joints[jj * 2 + 1]);

            float v = 0.0f;
            if (vis > 0) {
                int off = idx % RR;
                if (off < 0) off += RR;
                const int x = off % RES;     // first spatial axis (torch convention)
                const int y = off / RES;
                v = __ldg(tags + (size_t)b * AD * RR + (size_t)d * RR
                               + (size_t)x * RES + y);
            }
            sh[j][d] = v;
        }
        __syncthreads();

        // warp 0, lanes 0..16: column sums over joints -> g_psum
        if (tid < AD) {
            float s = 0.0f;
            #pragma unroll
            for (int j = 0; j < NJ; j++) s += sh[j][tid];
            g_psum[pt * AD + tid] = s;
        }

        // warp 1, lanes 0..16: per-joint s1/s2 -> sqv; plus valid flag;
        // masking makes sqv=0 for invisible joints automatically.
        if (tid >= 32 && tid < 64) {
            const int lane = tid - 32;
            float sqv = 0.0f, valid = 0.0f;
            if (lane < NJ) {
                const int j = lane;
                float s1 = 0.0f, s2 = 0.0f;
                #pragma unroll
                for (int d = 0; d < AD; d++) {
                    float v = sh[j][d];
                    s1 += v;
                    s2 += v * v;
                }
                sqv = 2.0f * (float)AD * s2 - 2.0f * s1 * s1;
                const int jj = b * JPI + m * NJ + j;
                valid = (__ldg(&joints[jj * 2 + 1]) > 0) ? 1.0f : 0.0f;
            }
            #pragma unroll
            for (int o = 16; o > 0; o >>= 1) {
                sqv   += __shfl_down_sync(FULL, sqv, o);
                valid += __shfl_down_sync(FULL, valid, o);
            }
            if (lane == 0) {
                g_psq [pt] = sqv;
                g_pcnt[pt] = valid;
            }
        }
        __syncthreads();

        if (tid == 0) {
            __threadfence();                 // publish stats
            atomicAdd(&g_done[b], 1u);
        }
        return;
    }

    // =============== REDUCE role: one image per CTA (blocks 0..15) =========
    const int b = blockIdx.x;

    __shared__ float mean_s[MP][AD];
    __shared__ float cnt_s[MP];
    __shared__ float pv[MP];
    __shared__ float sq_s[MP];
    __shared__ float ntags_s;
    __shared__ float push_acc;

    if (tid == 0) {
        push_acc = 0.0f;
        while (atomicAdd(&g_done[b], 0u) < (unsigned)MP) { }   // wait 30 producers
        g_done[b] = 0u;                      // reset for next graph replay
        __threadfence();                     // acquire
    }
    __syncthreads();

    if (tid < MP) {
        const float c = g_pcnt[b * MP + tid];
        cnt_s[tid] = c;
        sq_s[tid]  = g_psq[b * MP + tid];
        pv[tid]    = (c > 0.0f) ? 1.0f : 0.0f;
    }
    __syncthreads();

    if (tid < MP * AD) {
        const int m = tid / AD;
        mean_s[m][tid % AD] = g_psum[(b * MP) * AD + tid] / fmaxf(cnt_s[m], 1.0f);
    }

    // n_tags + pull on warp 0 (independent of mean computation above)
    if (tid < 32) {
        float nt = 0.0f, pl = 0.0f;
        if (tid < MP) {
            nt = pv[tid];
            pl = pv[tid] * sq_s[tid] / ((float)(AD * AD) * fmaxf(cnt_s[tid], 1.0f));
        }
        #pragma unroll
        for (int o = 16; o > 0; o >>= 1) {
            nt += __shfl_down_sync(FULL, nt, o);
            pl += __shfl_down_sync(FULL, pl, o);
        }
        if (tid == 0) {
            ntags_s = nt;
            out[BATCH + b] = pl / fmaxf(nt, 1.0f);   // pull[16]
        }
    }
    __syncthreads();

    // push: 900 ordered pairs (diagonal included), 2 per thread
    float acc = 0.0f;
    #pragma unroll
    for (int p = tid; p < MP * MP; p += BT) {
        const int m1 = p / MP;
        const int m2 = p % MP;
        const float w = pv[m1] * pv[m2];
        if (w != 0.0f) {
            float s = 0.0f;
            #pragma unroll
            for (int d = 0; d < AD; d++) {
                float df = mean_s[m1][d] - mean_s[m2][d];
                s += __expf(-df * df);
            }
            acc += s * (1.0f / (float)AD);
        }
    }
    #pragma unroll
    for (int o = 16; o > 0; o >>= 1)
        acc += __shfl_down_sync(FULL, acc, o);
    if ((tid & 31) == 0) atomicAdd(&push_acc, acc);
    __syncthreads();

    if (tid == 0) {
        const float nt = ntags_s;
        const float denom = fmaxf(nt, 1.0f);
        out[b] = (nt >= 2.0f) ? (push_acc / (denom * denom)) : 0.0f;  // push[16]
    }
}

extern "C" void kernel_launch(void* const* d_in, const int* in_sizes, int n_in,
                              void* d_out, int out_size)
{
    const float* tags   = (const float*)d_in[0];
    const int*   joints = (const int*)d_in[1];
    float*       out    = (float*)d_out;

    ae_onekernel<<<GRID_CTAS, BT>>>(tags, joints, out);
}